// round 2
// baseline (speedup 1.0000x reference)
#include <cuda_runtime.h>
#include <cstdint>

// ConditionalSplineSQ2D: out[b] = sum_{g,h,c} param[b,g,h,ii]*param[b,g,h,jj]*coef[g,h,c]
// B=4096, G*G=961 cells, P=8, C=36.
//
// HBM-bound (126 MB streamed once). R1's register prefetch left DRAM at 52%:
// only 8KB/SM in flight. This version decouples via a 7-stage cp.async.bulk
// (TMA) pipeline: param[b] is one contiguous 30752B slab -> one bulk copy per
// stage into a smem ring (215KB in flight/SM). Thread t keeps cell t's 36
// coefficients in registers; per b: 2x LDS.128, 44 FMA, block reduce.
// Producer = tid 992 (warp 31 leader, inactive cell). The per-iter
// __syncthreads (needed for the reduction anyway) is the ring drain point.

#define GG          961
#define CC          36
#define NTHR        1024
#define NSTAGE      7
#define STAGE_BYTES (GG * 32)          // 30752, multiple of 16
#define SMEM_DYN    (NSTAGE * STAGE_BYTES + 64)

extern __shared__ char dsmem[];

__device__ __forceinline__ uint32_t smem_u32(const void* p) {
    return (uint32_t)__cvta_generic_to_shared(p);
}

__device__ __forceinline__ void mbar_init(uint32_t mb, uint32_t count) {
    asm volatile("mbarrier.init.shared.b64 [%0], %1;" :: "r"(mb), "r"(count) : "memory");
}

__device__ __forceinline__ void bulk_load(uint32_t dst, const void* src,
                                          uint32_t bytes, uint32_t mb) {
    asm volatile(
        "mbarrier.arrive.expect_tx.shared.b64 _, [%3], %2;\n\t"
        "cp.async.bulk.shared::cta.global.mbarrier::complete_tx::bytes [%0], [%1], %2, [%3];"
        :: "r"(dst), "l"(src), "r"(bytes), "r"(mb) : "memory");
}

__device__ __forceinline__ void mbar_wait(uint32_t mb, uint32_t parity) {
    uint32_t done;
    asm volatile(
        "{\n\t.reg .pred p;\n\t"
        "mbarrier.try_wait.parity.acquire.cta.shared::cta.b64 p, [%1], %2;\n\t"
        "selp.b32 %0, 1, 0, p;\n\t}"
        : "=r"(done) : "r"(mb), "r"(parity) : "memory");
    if (!done) {
        asm volatile(
            "{\n\t.reg .pred P1;\n\t"
            "W_%=:\n\t"
            "mbarrier.try_wait.parity.acquire.cta.shared::cta.b64 P1, [%0], %1, 0x989680;\n\t"
            "@P1 bra.uni D_%=;\n\t"
            "bra.uni W_%=;\n\t"
            "D_%=:\n\t}"
            :: "r"(mb), "r"(parity) : "memory");
    }
}

__global__ __launch_bounds__(NTHR, 1)
void sq2d_kernel(const float* __restrict__ param,
                 const float* __restrict__ coef,
                 float* __restrict__ out,
                 int nB, int stride)
{
    __shared__ float red[2][32];

    char* stage_base = dsmem;
    char* mbar_base  = dsmem + NSTAGE * STAGE_BYTES;   // 8-aligned

    const int tid  = threadIdx.x;
    const int lane = tid & 31;
    const int warp = tid >> 5;
    const bool active = (tid < GG);
    const int cell = active ? tid : (GG - 1);
    const bool producer = (tid == 992);                 // warp 31 leader

    // Coefficients live in registers for the whole kernel (no L2 traffic amp).
    float cf[CC];
#pragma unroll
    for (int c = 0; c < CC; c++)
        cf[c] = active ? coef[cell * CC + c] : 0.0f;

    if (producer) {
        for (int s = 0; s < NSTAGE; s++)
            mbar_init(smem_u32(mbar_base + s * 8), 1);
    }
    __syncthreads();   // barrier init visible to all before any wait

    // Prefill the ring.
    if (producer) {
        int b = blockIdx.x;
        for (int s = 0; s < NSTAGE && b < nB; s++, b += stride) {
            bulk_load(smem_u32(stage_base) + s * STAGE_BYTES,
                      (const char*)param + (size_t)b * STAGE_BYTES,
                      STAGE_BYTES,
                      smem_u32(mbar_base + s * 8));
        }
    }

    int s = 0, ph = 0, buf = 0;
    for (int b = blockIdx.x; b < nB; b += stride) {
        mbar_wait(smem_u32(mbar_base + s * 8), ph);

        const float4* p4 = reinterpret_cast<const float4*>(stage_base + s * STAGE_BYTES)
                           + cell * 2;
        float4 a0 = p4[0];
        float4 a1 = p4[1];
        float pv[8] = { a0.x, a0.y, a0.z, a0.w, a1.x, a1.y, a1.z, a1.w };

        // acc = sum_{i<=j} cf[c(i,j)] * p_i * p_j : 44 FMA.
        float acc = 0.0f;
        int c = 0;
#pragma unroll
        for (int i = 0; i < 8; i++) {
            float q = 0.0f;
#pragma unroll
            for (int j = i; j < 8; j++)
                q = fmaf(cf[c++], pv[j], q);
            acc = fmaf(pv[i], q, acc);
        }

        // Warp reduce.
#pragma unroll
        for (int o = 16; o > 0; o >>= 1)
            acc += __shfl_xor_sync(0xffffffffu, acc, o);
        if (lane == 0) red[buf][warp] = acc;

        __syncthreads();   // all threads done reading stage s AND red written

        // Refill stage s for b + NSTAGE*stride (stage fully drained above).
        if (producer) {
            int bn = b + NSTAGE * stride;
            if (bn < nB) {
                bulk_load(smem_u32(stage_base) + s * STAGE_BYTES,
                          (const char*)param + (size_t)bn * STAGE_BYTES,
                          STAGE_BYTES,
                          smem_u32(mbar_base + s * 8));
            }
        }

        if (warp == 0) {
            float v = red[buf][lane];
#pragma unroll
            for (int o = 16; o > 0; o >>= 1)
                v += __shfl_xor_sync(0xffffffffu, v, o);
            if (lane == 0) out[b] = v;
        }

        buf ^= 1;
        s++;
        if (s == NSTAGE) { s = 0; ph ^= 1; }
    }
}

extern "C" void kernel_launch(void* const* d_in, const int* in_sizes, int n_in,
                              void* d_out, int out_size)
{
    const float* param = (const float*)d_in[0];   // [B, 31, 31, 8] f32
    const float* coef  = (const float*)d_in[1];   // [31, 31, 36]   f32
    float* out = (float*)d_out;                    // [B] f32

    const int nB = in_sizes[0] / (GG * 8);

    static int configured = -1;
    if (configured < 0) {
        cudaFuncSetAttribute(sq2d_kernel,
                             cudaFuncAttributeMaxDynamicSharedMemorySize, SMEM_DYN);
        configured = 1;
    }

    int dev = 0, sms = 0;
    cudaGetDevice(&dev);
    cudaDeviceGetAttribute(&sms, cudaDevAttrMultiProcessorCount, dev);
    if (sms <= 0) sms = 148;
    if (sms > nB) sms = nB;

    sq2d_kernel<<<sms, NTHR, SMEM_DYN>>>(param, coef, out, nB, sms);
}